// round 2
// baseline (speedup 1.0000x reference)
#include <cuda_runtime.h>
#include <cuda_fp16.h>
#include <cstdint>

#define HH 512
#define WW 512
#define BATCH 32
#define WPR 16                       // uint32 words per row (512 bits)
#define WORDS_PER_IMG (HH * WPR)     // 8192 words = 32KB
#define TILE_H 32
#define GRAY_ROWS (TILE_H + 4)       // 36
#define MAG_ROWS  (TILE_H + 2)       // 34
#define MAG_PITCH (WW + 2)           // 514 (zero cols at 0 and 513)
#define HPITCH 17                    // hysteresis exchange pitch (conflict-free)

// ---------------- device scratch (no allocations allowed) ----------------
__device__ uint32_t g_weak  [2 * BATCH * WORDS_PER_IMG];
__device__ uint32_t g_strong[2 * BATCH * WORDS_PER_IMG];
__device__ uint32_t g_edges [2 * BATCH * WORDS_PER_IMG];
__device__ unsigned int g_count;

// ---------------- fused gray -> sobel+class -> NMS -> threshold -> bitpack
__global__ __launch_bounds__(256) void k_frontend(const float* __restrict__ A,
                                                  const float* __restrict__ B) {
    extern __shared__ __half smemh[];
    __half* sg = smemh;                              // [GRAY_ROWS][WW]
    __half* sm = smemh + GRAY_ROWS * WW;             // [MAG_ROWS][MAG_PITCH]
    uint8_t* sd = (uint8_t*)(smemh + GRAY_ROWS * WW + MAG_ROWS * MAG_PITCH); // [TILE_H][WW]

    const int tid  = threadIdx.x;
    const int tile = blockIdx.x;
    const int b    = blockIdx.y;
    const int im   = blockIdx.z;
    const int r0   = tile * TILE_H;
    const float* img = (im == 0 ? A : B) + (size_t)b * 3 * HH * WW;

    if (tile == 0 && b == 0 && im == 0 && tid == 0) g_count = 0u;

    // Stage 1: quantized grayscale with reflect rows (halo 2)
    for (int idx = tid; idx < GRAY_ROWS * WW; idx += 256) {
        int rr = idx >> 9, c = idx & (WW - 1);
        int gr = r0 - 2 + rr;
        gr = gr < 0 ? -gr : (gr > HH - 1 ? 2 * (HH - 1) - gr : gr);
        const float* p = img + gr * WW + c;
        float r = p[0], g = p[HH * WW], bl = p[2 * HH * WW];
        // match XLA: ((0.299*R + 0.587*G) + 0.114*B), each op separately rounded
        float v = __fadd_rn(__fadd_rn(__fmul_rn(0.299f, r), __fmul_rn(0.587f, g)),
                            __fmul_rn(0.114f, bl));
        v = floorf(__fmul_rn(v, 255.0f));
        v = fminf(fmaxf(v, 0.0f), 255.0f);     // exact integer 0..255
        sg[idx] = __float2half_rn(v);          // exact in fp16
    }
    __syncthreads();

    // Stage 2: |gx|+|gy| magnitude (reflect cols) + direction class
    for (int idx = tid; idx < MAG_ROWS * WW; idx += 256) {
        int rr = idx >> 9, c = idx & (WW - 1);
        int gr = r0 - 1 + rr;
        float m = 0.0f;
        if (gr >= 0 && gr < HH) {
            int sr = rr + 1;                   // gray smem row for global row gr
            int cm = (c == 0) ? 1 : c - 1;
            int cp = (c == WW - 1) ? WW - 2 : c + 1;
            float a00 = __half2float(sg[(sr - 1) * WW + cm]);
            float a01 = __half2float(sg[(sr - 1) * WW + c ]);
            float a02 = __half2float(sg[(sr - 1) * WW + cp]);
            float a10 = __half2float(sg[ sr      * WW + cm]);
            float a12 = __half2float(sg[ sr      * WW + cp]);
            float a20 = __half2float(sg[(sr + 1) * WW + cm]);
            float a21 = __half2float(sg[(sr + 1) * WW + c ]);
            float a22 = __half2float(sg[(sr + 1) * WW + cp]);
            float gx = (a02 - a00) + 2.0f * (a12 - a10) + (a22 - a20);
            float gy = (a20 + 2.0f * a21 + a22) - (a00 + 2.0f * a01 + a02);
            float ax = fabsf(gx), ay = fabsf(gy);
            m = ax + ay;                       // exact integer <= 2040, exact in fp16
            if (rr >= 1 && rr <= TILE_H) {
                bool horiz = ay <= __fmul_rn((float)0.4142135623730951, ax);
                bool vert  = ay >= __fmul_rn((float)2.414213562373095,  ax);
                bool ss    = __fmul_rn(gx, gy) >= 0.0f;
                uint8_t cls = horiz ? 0 : (vert ? 1 : (ss ? 2 : 3));
                sd[(rr - 1) * WW + c] = cls;
            }
        }
        sm[rr * MAG_PITCH + c + 1] = __float2half_rn(m);
    }
    for (int rr = tid; rr < MAG_ROWS; rr += 256) {
        sm[rr * MAG_PITCH + 0]      = __float2half_rn(0.0f);
        sm[rr * MAG_PITCH + WW + 1] = __float2half_rn(0.0f);
    }
    __syncthreads();

    // Stage 3: NMS via class LUT + double threshold + ballot bitpack
    const int wid = tid >> 5, lane = tid & 31;
    const size_t obase = ((size_t)(im * BATCH + b)) * WORDS_PER_IMG;
    const __half h25 = __float2half_rn(25.0f);
    const __half h76 = __float2half_rn(76.0f);
    for (int t = wid; t < TILE_H * WPR; t += 8) {
        int rr = t >> 4, word = t & 15;
        int c = word * 32 + lane;
        int cls = sd[rr * WW + c];
        const __half* mp = sm + (rr + 1) * MAG_PITCH + (c + 1);
        // off1 = strict-side neighbor: h:W(-1) v:N(-514) d1:NW(-515) d2:NE(-513)
        int off1 = (cls == 0) ? -1 : (cls == 1) ? -MAG_PITCH
                 : (cls == 2) ? -(MAG_PITCH + 1) : -(MAG_PITCH - 1);
        __half m = mp[0];
        bool keep = __hgt(m, mp[off1]) && __hge(m, mp[-off1]);
        bool wk = keep && __hgt(m, h25);
        bool st = keep && __hgt(m, h76);
        unsigned wb = __ballot_sync(0xffffffffu, wk);
        unsigned sb = __ballot_sync(0xffffffffu, st);
        if (lane == 0) {
            g_weak  [obase + (size_t)(r0 + rr) * WPR + word] = wb;
            g_strong[obase + (size_t)(r0 + rr) * WPR + word] = sb;
        }
    }
}

// ---------------- bitwise hysteresis: 1 CTA/image, 1 row/thread, regs-resident
__global__ __launch_bounds__(512) void k_hyster() {
    extern __shared__ uint32_t sbuf[];   // 2 buffers of [512][HPITCH]
    const int t = threadIdx.x;           // row index 0..511
    const int im = blockIdx.x >> 5, b = blockIdx.x & 31;
    const size_t base = ((size_t)(im * BATCH + b)) * WORDS_PER_IMG + (size_t)t * WPR;

    uint32_t w[WPR], s[WPR], c[WPR];
    {
        const uint4* pw = (const uint4*)(g_weak + base);
        const uint4* ps = (const uint4*)(g_strong + base);
#pragma unroll
        for (int q = 0; q < 4; q++) {
            uint4 a = pw[q];
            w[4*q+0]=a.x; w[4*q+1]=a.y; w[4*q+2]=a.z; w[4*q+3]=a.w;
            uint4 d = ps[q];
            s[4*q+0]=d.x; s[4*q+1]=d.y; s[4*q+2]=d.z; s[4*q+3]=d.w;
        }
    }
#pragma unroll
    for (int i = 0; i < WPR; i++) c[i] = s[i];

    uint32_t* b0 = sbuf;
    uint32_t* b1 = sbuf + HH * HPITCH;
#pragma unroll
    for (int i = 0; i < WPR; i++) b0[t * HPITCH + i] = c[i];
    __syncthreads();

    for (int it = 0; it < 64; ++it) {
        const uint32_t* rd = (it & 1) ? b1 : b0;
        uint32_t*       wr = (it & 1) ? b0 : b1;
        const uint32_t* pu = rd + (t - 1) * HPITCH;
        const uint32_t* pd = rd + (t + 1) * HPITCH;
        uint32_t vor[WPR];
#pragma unroll
        for (int i = 0; i < WPR; i++) {
            uint32_t u = (t > 0)      ? pu[i] : 0u;
            uint32_t d = (t < HH - 1) ? pd[i] : 0u;
            vor[i] = u | d | c[i];               // vertical max (separable)
        }
        uint32_t ch = 0u;
#pragma unroll
        for (int i = 0; i < WPR; i++) {
            uint32_t lo = (i > 0)       ? vor[i - 1] : 0u;
            uint32_t hi = (i < WPR - 1) ? vor[i + 1] : 0u;
            uint32_t l = __funnelshift_l(lo, vor[i], 1);   // col-1 values
            uint32_t r = __funnelshift_r(vor[i], hi, 1);   // col+1 values
            uint32_t d3 = l | vor[i] | r;                  // 3x3 dilate done
            uint32_t nv = (d3 & w[i]) | s[i];
            ch |= nv ^ c[i];
            c[i] = nv;
            wr[t * HPITCH + i] = nv;
        }
        int any = __syncthreads_or((int)(ch != 0u));
        if (!any) break;  // fixed point => identical to reference while_loop
    }

    {
        uint4* pe = (uint4*)(g_edges + base);
#pragma unroll
        for (int q = 0; q < 4; q++)
            pe[q] = make_uint4(c[4*q+0], c[4*q+1], c[4*q+2], c[4*q+3]);
    }
}

// ---------------- XOR popcount reduction + sqrt ---------------------------
__global__ __launch_bounds__(256) void k_diff() {
    const int totalv = (BATCH * WORDS_PER_IMG) / 4;    // uint4 per image-set
    const uint4* ea = (const uint4*)g_edges;
    const uint4* eb = ea + totalv;
    int idx = blockIdx.x * blockDim.x + threadIdx.x;
    int sum = 0;
    for (int i = idx; i < totalv; i += gridDim.x * blockDim.x) {
        uint4 a = ea[i], d = eb[i];
        sum += __popc(a.x ^ d.x) + __popc(a.y ^ d.y)
             + __popc(a.z ^ d.z) + __popc(a.w ^ d.w);
    }
#pragma unroll
    for (int o = 16; o > 0; o >>= 1) sum += __shfl_down_sync(0xffffffffu, sum, o);
    __shared__ int wsum[8];
    int lane = threadIdx.x & 31, wq = threadIdx.x >> 5;
    if (lane == 0) wsum[wq] = sum;
    __syncthreads();
    if (threadIdx.x == 0) {
        int s2 = 0;
#pragma unroll
        for (int i = 0; i < 8; i++) s2 += wsum[i];
        atomicAdd(&g_count, (unsigned)s2);
    }
}

__global__ void k_final(float* out, int n) {
    float v = sqrtf((float)g_count);
    for (int i = threadIdx.x; i < n; i += blockDim.x) out[i] = v;
}

// ---------------- launch ---------------------------------------------------
extern "C" void kernel_launch(void* const* d_in, const int* in_sizes, int n_in,
                              void* d_out, int out_size) {
    const float* A = (const float*)d_in[0];
    const float* B = (const float*)d_in[1];

    size_t smemF = (size_t)(GRAY_ROWS * WW + MAG_ROWS * MAG_PITCH) * sizeof(__half)
                 + (size_t)TILE_H * WW;                    // ~88.2KB
    size_t smemH = (size_t)2 * HH * HPITCH * sizeof(uint32_t);  // 69,632B

    cudaFuncSetAttribute(k_frontend, cudaFuncAttributeMaxDynamicSharedMemorySize, (int)smemF);
    cudaFuncSetAttribute(k_hyster,   cudaFuncAttributeMaxDynamicSharedMemorySize, (int)smemH);

    k_frontend<<<dim3(HH / TILE_H, BATCH, 2), 256, smemF>>>(A, B);
    k_hyster<<<2 * BATCH, 512, smemH>>>();
    k_diff<<<256, 256>>>();
    k_final<<<1, 32>>>((float*)d_out, out_size);
}

// round 3
// speedup vs baseline: 1.9372x; 1.9372x over previous
#include <cuda_runtime.h>
#include <cuda_fp16.h>
#include <cstdint>

#define HH 512
#define WW 512
#define BATCH 32
#define WPR 16                       // uint32 words per row (512 bits)
#define WORDS_PER_IMG (HH * WPR)     // 8192 words = 32KB
#define TILE_H 32
#define GRAY_ROWS (TILE_H + 4)       // 36
#define MAG_ROWS  (TILE_H + 2)       // 34
#define MAG_PITCH (WW + 2)           // 514 (zero cols at 0 and 513)
#define HPITCH 17                    // hysteresis exchange pitch (conflict-free)
#define FTHREADS 512

// ---------------- device scratch (no allocations allowed) ----------------
__device__ uint32_t g_weak  [2 * BATCH * WORDS_PER_IMG];
__device__ uint32_t g_strong[2 * BATCH * WORDS_PER_IMG];
__device__ uint32_t g_edges [2 * BATCH * WORDS_PER_IMG];
__device__ unsigned int g_count;

// ---------------- fused gray -> sobel -> NMS -> threshold -> bitpack ------
// (R1 algorithm, 512 threads)
__global__ __launch_bounds__(FTHREADS) void k_frontend(const float* __restrict__ A,
                                                       const float* __restrict__ B) {
    extern __shared__ __half smemh[];
    __half* sg = smemh;                       // [GRAY_ROWS][WW]
    __half* sm = smemh + GRAY_ROWS * WW;      // [MAG_ROWS][MAG_PITCH]

    const int tid  = threadIdx.x;
    const int tile = blockIdx.x;
    const int b    = blockIdx.y;
    const int im   = blockIdx.z;
    const int r0   = tile * TILE_H;
    const float* img = (im == 0 ? A : B) + (size_t)b * 3 * HH * WW;

    if (tile == 0 && b == 0 && im == 0 && tid == 0) g_count = 0u;

    // Stage 1: quantized grayscale with reflect rows (halo 2)
    for (int idx = tid; idx < GRAY_ROWS * WW; idx += FTHREADS) {
        int rr = idx >> 9, c = idx & (WW - 1);
        int gr = r0 - 2 + rr;
        gr = gr < 0 ? -gr : (gr > HH - 1 ? 2 * (HH - 1) - gr : gr);
        const float* p = img + gr * WW + c;
        float r = p[0], g = p[HH * WW], bl = p[2 * HH * WW];
        // match XLA: ((0.299*R + 0.587*G) + 0.114*B), each op separately rounded
        float v = __fadd_rn(__fadd_rn(__fmul_rn(0.299f, r), __fmul_rn(0.587f, g)),
                            __fmul_rn(0.114f, bl));
        v = floorf(__fmul_rn(v, 255.0f));
        v = fminf(fmaxf(v, 0.0f), 255.0f);     // exact integer 0..255
        sg[idx] = __float2half_rn(v);          // exact in fp16
    }
    __syncthreads();

    // Stage 2: |gx|+|gy| magnitude (reflect cols), zero outside the image
    for (int idx = tid; idx < MAG_ROWS * WW; idx += FTHREADS) {
        int rr = idx >> 9, c = idx & (WW - 1);
        int gr = r0 - 1 + rr;
        float m = 0.0f;
        if (gr >= 0 && gr < HH) {
            int sr = rr + 1;                   // gray smem row for global row gr
            int cm = (c == 0) ? 1 : c - 1;
            int cp = (c == WW - 1) ? WW - 2 : c + 1;
            float a00 = __half2float(sg[(sr - 1) * WW + cm]);
            float a01 = __half2float(sg[(sr - 1) * WW + c ]);
            float a02 = __half2float(sg[(sr - 1) * WW + cp]);
            float a10 = __half2float(sg[ sr      * WW + cm]);
            float a12 = __half2float(sg[ sr      * WW + cp]);
            float a20 = __half2float(sg[(sr + 1) * WW + cm]);
            float a21 = __half2float(sg[(sr + 1) * WW + c ]);
            float a22 = __half2float(sg[(sr + 1) * WW + cp]);
            float gx = (a02 - a00) + 2.0f * (a12 - a10) + (a22 - a20);
            float gy = (a20 + 2.0f * a21 + a22) - (a00 + 2.0f * a01 + a02);
            m = fabsf(gx) + fabsf(gy);         // exact integer <= 2040, exact in fp16
        }
        sm[rr * MAG_PITCH + c + 1] = __float2half_rn(m);
    }
    for (int rr = tid; rr < MAG_ROWS; rr += FTHREADS) {
        sm[rr * MAG_PITCH + 0]      = __float2half_rn(0.0f);
        sm[rr * MAG_PITCH + WW + 1] = __float2half_rn(0.0f);
    }
    __syncthreads();

    // Stage 3: NMS + double threshold + ballot bitpack (register Sobel recompute)
    const int wid = tid >> 5, lane = tid & 31;
    const int nwarps = FTHREADS / 32;
    const size_t obase = ((size_t)(im * BATCH + b)) * WORDS_PER_IMG;
#define SMV(r_, c_) __half2float(sm[(r_) * MAG_PITCH + (c_) + 1])
    for (int t = wid; t < TILE_H * WPR; t += nwarps) {
        int rr = t >> 4, word = t & 15;
        int c = word * 32 + lane;
        int sr = rr + 2;                        // gray smem row for output row
        int cm = (c == 0) ? 1 : c - 1;
        int cp = (c == WW - 1) ? WW - 2 : c + 1;
        float a00 = __half2float(sg[(sr - 1) * WW + cm]);
        float a01 = __half2float(sg[(sr - 1) * WW + c ]);
        float a02 = __half2float(sg[(sr - 1) * WW + cp]);
        float a10 = __half2float(sg[ sr      * WW + cm]);
        float a12 = __half2float(sg[ sr      * WW + cp]);
        float a20 = __half2float(sg[(sr + 1) * WW + cm]);
        float a21 = __half2float(sg[(sr + 1) * WW + c ]);
        float a22 = __half2float(sg[(sr + 1) * WW + cp]);
        float gx = (a02 - a00) + 2.0f * (a12 - a10) + (a22 - a20);
        float gy = (a20 + 2.0f * a21 + a22) - (a00 + 2.0f * a01 + a02);
        float ax = fabsf(gx), ay = fabsf(gy);
        float mag = ax + ay;
        float mW  = SMV(rr + 1, c - 1), mE  = SMV(rr + 1, c + 1);
        float mN  = SMV(rr,     c    ), mS  = SMV(rr + 2, c    );
        float mNW = SMV(rr,     c - 1), mSE = SMV(rr + 2, c + 1);
        float mNE = SMV(rr,     c + 1), mSW = SMV(rr + 2, c - 1);
        bool horiz = ay <= __fmul_rn((float)0.4142135623730951, ax);
        bool vert  = ay >= __fmul_rn((float)2.414213562373095,  ax);
        bool ss    = __fmul_rn(gx, gy) >= 0.0f;
        bool keep;
        if (horiz)      keep = (mag > mW)  & (mag >= mE);
        else if (vert)  keep = (mag > mN)  & (mag >= mS);
        else if (ss)    keep = (mag > mNW) & (mag >= mSE);
        else            keep = (mag > mNE) & (mag >= mSW);
        bool wk = keep && (mag > 25.0f);
        bool st = keep && (mag > 76.0f);
        unsigned wb = __ballot_sync(0xffffffffu, wk);
        unsigned sb = __ballot_sync(0xffffffffu, st);
        if (lane == 0) {
            g_weak  [obase + (size_t)(r0 + rr) * WPR + word] = wb;
            g_strong[obase + (size_t)(r0 + rr) * WPR + word] = sb;
        }
    }
#undef SMV
}

// ---------------- bitwise hysteresis: 1 CTA/image, 1 row/thread, regs-resident
__global__ __launch_bounds__(512) void k_hyster() {
    extern __shared__ uint32_t sbuf[];   // 2 buffers of [512][HPITCH]
    const int t = threadIdx.x;           // row index 0..511
    const int im = blockIdx.x >> 5, b = blockIdx.x & 31;
    const size_t base = ((size_t)(im * BATCH + b)) * WORDS_PER_IMG + (size_t)t * WPR;

    uint32_t w[WPR], s[WPR], c[WPR];
    {
        const uint4* pw = (const uint4*)(g_weak + base);
        const uint4* ps = (const uint4*)(g_strong + base);
#pragma unroll
        for (int q = 0; q < 4; q++) {
            uint4 a = pw[q];
            w[4*q+0]=a.x; w[4*q+1]=a.y; w[4*q+2]=a.z; w[4*q+3]=a.w;
            uint4 d = ps[q];
            s[4*q+0]=d.x; s[4*q+1]=d.y; s[4*q+2]=d.z; s[4*q+3]=d.w;
        }
    }
#pragma unroll
    for (int i = 0; i < WPR; i++) c[i] = s[i];

    uint32_t* b0 = sbuf;
    uint32_t* b1 = sbuf + HH * HPITCH;
#pragma unroll
    for (int i = 0; i < WPR; i++) b0[t * HPITCH + i] = c[i];
    __syncthreads();

    for (int it = 0; it < 64; ++it) {
        const uint32_t* rd = (it & 1) ? b1 : b0;
        uint32_t*       wr = (it & 1) ? b0 : b1;
        const uint32_t* pu = rd + (t - 1) * HPITCH;
        const uint32_t* pd = rd + (t + 1) * HPITCH;
        uint32_t vor[WPR];
#pragma unroll
        for (int i = 0; i < WPR; i++) {
            uint32_t u = (t > 0)      ? pu[i] : 0u;
            uint32_t d = (t < HH - 1) ? pd[i] : 0u;
            vor[i] = u | d | c[i];               // vertical max (separable)
        }
        uint32_t ch = 0u;
#pragma unroll
        for (int i = 0; i < WPR; i++) {
            uint32_t lo = (i > 0)       ? vor[i - 1] : 0u;
            uint32_t hi = (i < WPR - 1) ? vor[i + 1] : 0u;
            uint32_t l = __funnelshift_l(lo, vor[i], 1);   // col-1 values
            uint32_t r = __funnelshift_r(vor[i], hi, 1);   // col+1 values
            uint32_t d3 = l | vor[i] | r;                  // 3x3 dilate done
            uint32_t nv = (d3 & w[i]) | s[i];
            ch |= nv ^ c[i];
            c[i] = nv;
            wr[t * HPITCH + i] = nv;
        }
        int any = __syncthreads_or((int)(ch != 0u));
        if (!any) break;  // fixed point => identical to reference while_loop
    }

    {
        uint4* pe = (uint4*)(g_edges + base);
#pragma unroll
        for (int q = 0; q < 4; q++)
            pe[q] = make_uint4(c[4*q+0], c[4*q+1], c[4*q+2], c[4*q+3]);
    }
}

// ---------------- XOR popcount reduction + sqrt ---------------------------
__global__ __launch_bounds__(256) void k_diff() {
    const int totalv = (BATCH * WORDS_PER_IMG) / 4;    // uint4 per image-set
    const uint4* ea = (const uint4*)g_edges;
    const uint4* eb = ea + totalv;
    int idx = blockIdx.x * blockDim.x + threadIdx.x;
    int sum = 0;
    for (int i = idx; i < totalv; i += gridDim.x * blockDim.x) {
        uint4 a = ea[i], d = eb[i];
        sum += __popc(a.x ^ d.x) + __popc(a.y ^ d.y)
             + __popc(a.z ^ d.z) + __popc(a.w ^ d.w);
    }
#pragma unroll
    for (int o = 16; o > 0; o >>= 1) sum += __shfl_down_sync(0xffffffffu, sum, o);
    __shared__ int wsum[8];
    int lane = threadIdx.x & 31, wq = threadIdx.x >> 5;
    if (lane == 0) wsum[wq] = sum;
    __syncthreads();
    if (threadIdx.x == 0) {
        int s2 = 0;
#pragma unroll
        for (int i = 0; i < 8; i++) s2 += wsum[i];
        atomicAdd(&g_count, (unsigned)s2);
    }
}

__global__ void k_final(float* out, int n) {
    float v = sqrtf((float)g_count);
    for (int i = threadIdx.x; i < n; i += blockDim.x) out[i] = v;
}

// ---------------- launch ---------------------------------------------------
extern "C" void kernel_launch(void* const* d_in, const int* in_sizes, int n_in,
                              void* d_out, int out_size) {
    const float* A = (const float*)d_in[0];
    const float* B = (const float*)d_in[1];

    size_t smemF = (size_t)(GRAY_ROWS * WW + MAG_ROWS * MAG_PITCH) * sizeof(__half); // ~71.8KB
    size_t smemH = (size_t)2 * HH * HPITCH * sizeof(uint32_t);                       // 69,632B

    cudaFuncSetAttribute(k_frontend, cudaFuncAttributeMaxDynamicSharedMemorySize, (int)smemF);
    cudaFuncSetAttribute(k_hyster,   cudaFuncAttributeMaxDynamicSharedMemorySize, (int)smemH);

    k_frontend<<<dim3(HH / TILE_H, BATCH, 2), FTHREADS, smemF>>>(A, B);
    k_hyster<<<2 * BATCH, 512, smemH>>>();
    k_diff<<<256, 256>>>();
    k_final<<<1, 32>>>((float*)d_out, out_size);
}